// round 16
// baseline (speedup 1.0000x reference)
#include <cuda_runtime.h>
#include <math_constants.h>

// Split-K persistent MAM-GEMM + fma-offload + packed f32x2 mul/add.
// Row-pair vectorization: (a_i, a_i+1) is a natural register pair; B is stored
// DUPLICATED in smem as (b_j, b_j) pairs so packed FMUL needs no pack MOVs.
// Per 4 products: fma = 2 packed MUL + 1 packed ADD + 2 FSUB = 5 instr,
// alu = 2 max + 4 accum = 6 instr  ->  alu-bound at 1.5 instr/product.
// min(p0,p1) = (p0+p1) - max(p0,p1) as in R14 (rel_err ~5e-8).

#define TBM 128
#define TBN 64
#define BK  16
#define TM  8
#define TN  4
#define SA  132     // A smem stride (floats); %4==0 -> 16B-aligned rows
#define SBD 132     // B DUP smem stride (floats): 128 dup floats + 4 pad
#define NUM_SMS 148
#define SPLITS  4
#define THREADS 256

#define MM 2048
#define NN 1024
#define NTILES ((MM / TBM) * (NN / TBN))   // 256

typedef unsigned long long ull;

__device__ __forceinline__ ull mul2(ull a, ull b) {
    ull d; asm("mul.rn.f32x2 %0, %1, %2;" : "=l"(d) : "l"(a), "l"(b)); return d;
}
__device__ __forceinline__ ull add2(ull a, ull b) {
    ull d; asm("add.rn.f32x2 %0, %1, %2;" : "=l"(d) : "l"(a), "l"(b)); return d;
}
__device__ __forceinline__ void unpack2(ull v, float& lo, float& hi) {
    asm("mov.b64 {%0, %1}, %2;" : "=f"(lo), "=f"(hi) : "l"(v));
}

__device__ float g_mx[SPLITS][MM * NN];    // 32 MB
__device__ float g_mn[SPLITS][MM * NN];    // 32 MB
__device__ unsigned int g_cnt[NTILES];     // zeroed at load; finisher resets -> replay-safe

__global__ __launch_bounds__(THREADS, 1)
void mam_kernel(const float* __restrict__ A,    // [M, K]
                const float* __restrict__ W,    // [N, K]
                const float* __restrict__ bias, // [N]
                float* __restrict__ C,          // [M, N]
                int M, int N, int K)
{
    __shared__ float As[2][BK * SA];   // As[buf][k*SA + m]
    __shared__ float Bsd[2][BK * SBD]; // Bsd[buf][k*SBD + 2*n] = Bsd[..+2*n+1] = b_n
    __shared__ unsigned int s_old;

    const int tid = threadIdx.x;
    const int tx  = tid & 15;    // 16 col-groups of TN=4 -> 64 cols
    const int ty  = tid >> 4;    // 16 row-groups of TM=8 -> 128 rows

    // A staging: 128x16 floats = 256 threads x 2 float4 (rows ar, ar+64)
    const int ar  = tid >> 2;         // 0..63
    const int akc = (tid & 3) * 4;    // 0,4,8,12
    // B staging: 64x16 floats = 256 threads x 1 float4 (duplicated on store)
    const int br  = tid >> 2;         // 0..63
    const int bkc = (tid & 3) * 4;

    const int tilesN  = N / TBN;                  // 16
    const int nTiles  = (M / TBM) * tilesN;       // 256
    const int nItems  = nTiles * SPLITS;          // 1024
    const int kPart   = K / SPLITS;               // 256
    const int nK      = kPart / BK;               // 16

    for (int t = blockIdx.x; t < nItems; t += NUM_SMS) {
        const int tile  = t & (nTiles - 1);
        const int split = t >> 8;
        const int mi = tile >> 4;
        const int ni = tile & 15;
        const int kbase = split * kPart;

        const float* Aptr = A + (size_t)(mi * TBM + ar) * K + kbase + akc;
        const float* Wptr = W + (size_t)(ni * TBN + br) * K + kbase + bkc;
        const size_t arowskip = (size_t)64 * K;

        float mx[TM][TN], mn[TM][TN];
#pragma unroll
        for (int i = 0; i < TM; ++i)
#pragma unroll
            for (int j = 0; j < TN; ++j) {
                mx[i][j] = -CUDART_INF_F;
                mn[i][j] =  CUDART_INF_F;
            }

        // ---- prologue: stage k-slice 0 into buf 0 ----
        float4 pa0 = *(const float4*)(Aptr);
        float4 pa1 = *(const float4*)(Aptr + arowskip);
        float4 pb  = *(const float4*)(Wptr);
        {
            float* as = As[0]; float* bs = Bsd[0];
            as[(akc + 0) * SA + ar] = pa0.x;
            as[(akc + 1) * SA + ar] = pa0.y;
            as[(akc + 2) * SA + ar] = pa0.z;
            as[(akc + 3) * SA + ar] = pa0.w;
            as[(akc + 0) * SA + ar + 64] = pa1.x;
            as[(akc + 1) * SA + ar + 64] = pa1.y;
            as[(akc + 2) * SA + ar + 64] = pa1.z;
            as[(akc + 3) * SA + ar + 64] = pa1.w;
            *(float2*)&bs[(bkc + 0) * SBD + 2 * br] = make_float2(pb.x, pb.x);
            *(float2*)&bs[(bkc + 1) * SBD + 2 * br] = make_float2(pb.y, pb.y);
            *(float2*)&bs[(bkc + 2) * SBD + 2 * br] = make_float2(pb.z, pb.z);
            *(float2*)&bs[(bkc + 3) * SBD + 2 * br] = make_float2(pb.w, pb.w);
        }
        __syncthreads();

        for (int kt = 0; kt < nK; ++kt) {
            const int buf = kt & 1;

            if (kt + 1 < nK) {
                const int k0 = (kt + 1) * BK;
                pa0 = *(const float4*)(Aptr + k0);
                pa1 = *(const float4*)(Aptr + arowskip + k0);
                pb  = *(const float4*)(Wptr + k0);
            }

            const float* as = As[buf];
            const float* bs = Bsd[buf];

            // ---- compute: 2 k-steps, row-pair packed ----
#pragma unroll
            for (int k = 0; k < BK; k += 2) {
                // a rows: 8 floats = 4 natural pairs, per k
                ulonglong2 a0v0 = *(const ulonglong2*)&as[k * SA + ty * TM];
                ulonglong2 a0v1 = *(const ulonglong2*)&as[k * SA + ty * TM + 4];
                ulonglong2 a1v0 = *(const ulonglong2*)&as[(k + 1) * SA + ty * TM];
                ulonglong2 a1v1 = *(const ulonglong2*)&as[(k + 1) * SA + ty * TM + 4];
                ull ap0[4] = { a0v0.x, a0v0.y, a0v1.x, a0v1.y };
                ull ap1[4] = { a1v0.x, a1v0.y, a1v1.x, a1v1.y };
                // b dup: 4 cols -> 8 floats = 4 (b,b) pairs, per k
                ulonglong2 b0v0 = *(const ulonglong2*)&bs[k * SBD + tx * 8];
                ulonglong2 b0v1 = *(const ulonglong2*)&bs[k * SBD + tx * 8 + 4];
                ulonglong2 b1v0 = *(const ulonglong2*)&bs[(k + 1) * SBD + tx * 8];
                ulonglong2 b1v1 = *(const ulonglong2*)&bs[(k + 1) * SBD + tx * 8 + 4];
                ull bd0[4] = { b0v0.x, b0v0.y, b0v1.x, b0v1.y };
                ull bd1[4] = { b1v0.x, b1v0.y, b1v1.x, b1v1.y };

#pragma unroll
                for (int ip = 0; ip < 4; ++ip)        // row pairs (2ip, 2ip+1)
#pragma unroll
                    for (int j = 0; j < TN; ++j) {
                        ull p0 = mul2(ap0[ip], bd0[j]);   // fma (packed)
                        ull p1 = mul2(ap1[ip], bd1[j]);   // fma (packed)
                        ull s  = add2(p0, p1);            // fma (packed)
                        float p0l, p0h, p1l, p1h, sl, sh;
                        unpack2(p0, p0l, p0h);
                        unpack2(p1, p1l, p1h);
                        unpack2(s,  sl,  sh);
                        float hl = fmaxf(p0l, p1l);       // alu
                        float hh = fmaxf(p0h, p1h);       // alu
                        mx[2*ip  ][j] = fmaxf(mx[2*ip  ][j], hl);   // alu
                        mx[2*ip+1][j] = fmaxf(mx[2*ip+1][j], hh);   // alu
                        mn[2*ip  ][j] = fminf(mn[2*ip  ][j], sl - hl); // fma + alu
                        mn[2*ip+1][j] = fminf(mn[2*ip+1][j], sh - hh); // fma + alu
                    }
            }

            if (kt + 1 < nK) {
                float* asw = As[buf ^ 1]; float* bsw = Bsd[buf ^ 1];
                asw[(akc + 0) * SA + ar] = pa0.x;
                asw[(akc + 1) * SA + ar] = pa0.y;
                asw[(akc + 2) * SA + ar] = pa0.z;
                asw[(akc + 3) * SA + ar] = pa0.w;
                asw[(akc + 0) * SA + ar + 64] = pa1.x;
                asw[(akc + 1) * SA + ar + 64] = pa1.y;
                asw[(akc + 2) * SA + ar + 64] = pa1.z;
                asw[(akc + 3) * SA + ar + 64] = pa1.w;
                *(float2*)&bsw[(bkc + 0) * SBD + 2 * br] = make_float2(pb.x, pb.x);
                *(float2*)&bsw[(bkc + 1) * SBD + 2 * br] = make_float2(pb.y, pb.y);
                *(float2*)&bsw[(bkc + 2) * SBD + 2 * br] = make_float2(pb.z, pb.z);
                *(float2*)&bsw[(bkc + 3) * SBD + 2 * br] = make_float2(pb.w, pb.w);
                __syncthreads();
            }
        }

        // ---- epilogue: exclusive-owner partial stores ----
        const int row0 = mi * TBM + ty * TM;
        const int col0 = ni * TBN + tx * TN;
        float* mxp = g_mx[split] + (size_t)row0 * N + col0;
        float* mnp = g_mn[split] + (size_t)row0 * N + col0;
#pragma unroll
        for (int i = 0; i < TM; ++i) {
            *(float4*)(mxp + (size_t)i * N) = make_float4(mx[i][0], mx[i][1], mx[i][2], mx[i][3]);
            *(float4*)(mnp + (size_t)i * N) = make_float4(mn[i][0], mn[i][1], mn[i][2], mn[i][3]);
        }

        // ---- arrival protocol ----
        __threadfence();
        __syncthreads();
        if (tid == 0) s_old = atomicAdd(&g_cnt[tile], 1u);
        __syncthreads();

        if (s_old == SPLITS - 1) {
            // ---- finisher: merge 4 partials + bias -> C ----
            __threadfence();
            const int rowbase = mi * TBM;
            const int colbase = ni * TBN;
#pragma unroll
            for (int it = 0; it < 8; ++it) {
                const int e = it * 1024 + tid * 4;
                const int r = e >> 6;
                const int c = e & 63;
                const size_t off = (size_t)(rowbase + r) * N + colbase + c;

                float4 x0 = *(const float4*)(g_mx[0] + off);
                float4 x1 = *(const float4*)(g_mx[1] + off);
                float4 x2 = *(const float4*)(g_mx[2] + off);
                float4 x3 = *(const float4*)(g_mx[3] + off);
                float4 n0 = *(const float4*)(g_mn[0] + off);
                float4 n1 = *(const float4*)(g_mn[1] + off);
                float4 n2 = *(const float4*)(g_mn[2] + off);
                float4 n3 = *(const float4*)(g_mn[3] + off);
                float4 bv = *(const float4*)&bias[colbase + c];

                float4 o;
                o.x = fmaxf(fmaxf(x0.x, x1.x), fmaxf(x2.x, x3.x)) + fminf(fminf(n0.x, n1.x), fminf(n2.x, n3.x)) + bv.x;
                o.y = fmaxf(fmaxf(x0.y, x1.y), fmaxf(x2.y, x3.y)) + fminf(fminf(n0.y, n1.y), fminf(n2.y, n3.y)) + bv.y;
                o.z = fmaxf(fmaxf(x0.z, x1.z), fmaxf(x2.z, x3.z)) + fminf(fminf(n0.z, n1.z), fminf(n2.z, n3.z)) + bv.z;
                o.w = fmaxf(fmaxf(x0.w, x1.w), fmaxf(x2.w, x3.w)) + fminf(fminf(n0.w, n1.w), fminf(n2.w, n3.w)) + bv.w;
                *(float4*)(C + off) = o;
            }
            if (tid == 0) g_cnt[tile] = 0;
        }
    }
}

extern "C" void kernel_launch(void* const* d_in, const int* in_sizes, int n_in,
                              void* d_out, int out_size)
{
    const float* x    = (const float*)d_in[0];   // [M, K]
    const float* w    = (const float*)d_in[1];   // [N, K]
    const float* bias = (const float*)d_in[2];   // [N]
    float* out = (float*)d_out;

    const int N = in_sizes[2];                  // 1024
    const int K = in_sizes[1] / N;              // 1024
    const int M = in_sizes[0] / K;              // 2048

    mam_kernel<<<NUM_SMS, THREADS>>>(x, w, bias, out, M, N, K);
}

// round 17
// speedup vs baseline: 1.1647x; 1.1647x over previous
#include <cuda_runtime.h>
#include <math_constants.h>

// Split-K persistent MAM-GEMM: R14's fma-offload trick (TRICK_ROWS=5) on
// R13's 2-CTAs-per-SM skeleton. Rationale: the trick kernel is issue-stall
// limited (issue 70%, both pipes < 60%), so 4 warps/SMSP from two INDEPENDENT
// CTAs (no shared barrier) fill the dependency/barrier windows.
// 512 tiles of 64x64 x 4 K-splits = 2048 items over 296 persistent CTAs.

#define TBM 64
#define TBN 64
#define BK  16
#define TM  8
#define TN  4
#define TRICK_ROWS 5
#define SA  68      // 68*4 % 16 == 0 -> LDS.128 aligned
#define NUM_CTAS 296
#define SPLITS  4
#define THREADS 128

#define MM 2048
#define NN 1024
#define NTILES ((MM / TBM) * (NN / TBN))   // 512

__device__ float g_mx[SPLITS][MM * NN];    // 32 MB
__device__ float g_mn[SPLITS][MM * NN];    // 32 MB
__device__ unsigned int g_cnt[NTILES];     // zeroed at load; finisher resets -> replay-safe

__global__ __launch_bounds__(THREADS, 2)
void mam_kernel(const float* __restrict__ A,    // [M, K]
                const float* __restrict__ W,    // [N, K]
                const float* __restrict__ bias, // [N]
                float* __restrict__ C,          // [M, N]
                int M, int N, int K)
{
    __shared__ float As[2][BK * SA];  // As[buf][k*SA + m]
    __shared__ float Bs[2][BK * SA];  // Bs[buf][k*SA + n]
    __shared__ unsigned int s_old;

    const int tid = threadIdx.x;
    const int tx  = tid & 15;    // 16 col-groups of TN=4 -> 64 cols
    const int ty  = tid >> 4;    // 8 row-groups of TM=8 -> 64 rows

    // staging: 64x16 floats per operand = 128 threads x 2 float4 (rows lr, lr+32)
    const int lr  = tid >> 2;         // 0..31
    const int lkc = (tid & 3) * 4;    // 0,4,8,12

    const int tilesN  = N / TBN;                  // 16
    const int nTiles  = (M / TBM) * tilesN;       // 512
    const int nItems  = nTiles * SPLITS;          // 2048
    const int kPart   = K / SPLITS;               // 256
    const int nK      = kPart / BK;               // 16

    for (int t = blockIdx.x; t < nItems; t += NUM_CTAS) {
        const int tile  = t & (nTiles - 1);
        const int split = t >> 9;                 // t / 512
        const int mi = tile >> 4;
        const int ni = tile & 15;
        const int kbase = split * kPart;

        const float* Aptr = A + (size_t)(mi * TBM + lr) * K + kbase + lkc;
        const float* Wptr = W + (size_t)(ni * TBN + lr) * K + kbase + lkc;
        const size_t rowskip = (size_t)32 * K;

        float mx[TM][TN], mn[TM][TN];
#pragma unroll
        for (int i = 0; i < TM; ++i)
#pragma unroll
            for (int j = 0; j < TN; ++j) {
                mx[i][j] = -CUDART_INF_F;
                mn[i][j] =  CUDART_INF_F;
            }

        // ---- prologue: stage k-slice 0 into buf 0 ----
        float4 pa0 = *(const float4*)(Aptr);
        float4 pa1 = *(const float4*)(Aptr + rowskip);
        float4 pb0 = *(const float4*)(Wptr);
        float4 pb1 = *(const float4*)(Wptr + rowskip);
        {
            float* as = As[0]; float* bs = Bs[0];
            as[(lkc + 0) * SA + lr] = pa0.x;
            as[(lkc + 1) * SA + lr] = pa0.y;
            as[(lkc + 2) * SA + lr] = pa0.z;
            as[(lkc + 3) * SA + lr] = pa0.w;
            as[(lkc + 0) * SA + lr + 32] = pa1.x;
            as[(lkc + 1) * SA + lr + 32] = pa1.y;
            as[(lkc + 2) * SA + lr + 32] = pa1.z;
            as[(lkc + 3) * SA + lr + 32] = pa1.w;
            bs[(lkc + 0) * SA + lr] = pb0.x;
            bs[(lkc + 1) * SA + lr] = pb0.y;
            bs[(lkc + 2) * SA + lr] = pb0.z;
            bs[(lkc + 3) * SA + lr] = pb0.w;
            bs[(lkc + 0) * SA + lr + 32] = pb1.x;
            bs[(lkc + 1) * SA + lr + 32] = pb1.y;
            bs[(lkc + 2) * SA + lr + 32] = pb1.z;
            bs[(lkc + 3) * SA + lr + 32] = pb1.w;
        }
        __syncthreads();

        for (int kt = 0; kt < nK; ++kt) {
            const int buf = kt & 1;

            if (kt + 1 < nK) {
                const int k0 = (kt + 1) * BK;
                pa0 = *(const float4*)(Aptr + k0);
                pa1 = *(const float4*)(Aptr + rowskip + k0);
                pb0 = *(const float4*)(Wptr + k0);
                pb1 = *(const float4*)(Wptr + rowskip + k0);
            }

            const float* as = As[buf];
            const float* bs = Bs[buf];

            // ---- compute: 2 k-steps at a time, fma-offloaded min for i<TRICK_ROWS ----
#pragma unroll
            for (int k = 0; k < BK; k += 2) {
                float a0[TM], b0[TN], a1[TM], b1[TN];
                *(float4*)&a0[0] = *(const float4*)&as[k * SA + ty * TM];
                *(float4*)&a0[4] = *(const float4*)&as[k * SA + ty * TM + 4];
                *(float4*)&b0[0] = *(const float4*)&bs[k * SA + tx * TN];
                *(float4*)&a1[0] = *(const float4*)&as[(k + 1) * SA + ty * TM];
                *(float4*)&a1[4] = *(const float4*)&as[(k + 1) * SA + ty * TM + 4];
                *(float4*)&b1[0] = *(const float4*)&bs[(k + 1) * SA + tx * TN];

#pragma unroll
                for (int i = 0; i < TM; ++i) {
                    if (i < TRICK_ROWS) {
#pragma unroll
                        for (int j = 0; j < TN; ++j) {
                            float p0 = a0[i] * b0[j];          // fma
                            float p1 = a1[i] * b1[j];          // fma
                            float hi = fmaxf(p0, p1);          // alu
                            float s  = p0 + p1;                // fma
                            float lo = s - hi;                 // fma (= min(p0,p1))
                            mx[i][j] = fmaxf(mx[i][j], hi);    // alu
                            mn[i][j] = fminf(mn[i][j], lo);    // alu
                        }
                    } else {
#pragma unroll
                        for (int j = 0; j < TN; ++j) {
                            float p0 = a0[i] * b0[j];
                            float p1 = a1[i] * b1[j];
                            mx[i][j] = fmaxf(mx[i][j], fmaxf(p0, p1));
                            mn[i][j] = fminf(mn[i][j], fminf(p0, p1));
                        }
                    }
                }
            }

            if (kt + 1 < nK) {
                float* asw = As[buf ^ 1]; float* bsw = Bs[buf ^ 1];
                asw[(lkc + 0) * SA + lr] = pa0.x;
                asw[(lkc + 1) * SA + lr] = pa0.y;
                asw[(lkc + 2) * SA + lr] = pa0.z;
                asw[(lkc + 3) * SA + lr] = pa0.w;
                asw[(lkc + 0) * SA + lr + 32] = pa1.x;
                asw[(lkc + 1) * SA + lr + 32] = pa1.y;
                asw[(lkc + 2) * SA + lr + 32] = pa1.z;
                asw[(lkc + 3) * SA + lr + 32] = pa1.w;
                bsw[(lkc + 0) * SA + lr] = pb0.x;
                bsw[(lkc + 1) * SA + lr] = pb0.y;
                bsw[(lkc + 2) * SA + lr] = pb0.z;
                bsw[(lkc + 3) * SA + lr] = pb0.w;
                bsw[(lkc + 0) * SA + lr + 32] = pb1.x;
                bsw[(lkc + 1) * SA + lr + 32] = pb1.y;
                bsw[(lkc + 2) * SA + lr + 32] = pb1.z;
                bsw[(lkc + 3) * SA + lr + 32] = pb1.w;
                __syncthreads();
            }
        }

        // ---- epilogue: exclusive-owner partial stores ----
        const int row0 = mi * TBM + ty * TM;
        const int col0 = ni * TBN + tx * TN;
        float* mxp = g_mx[split] + (size_t)row0 * N + col0;
        float* mnp = g_mn[split] + (size_t)row0 * N + col0;
#pragma unroll
        for (int i = 0; i < TM; ++i) {
            *(float4*)(mxp + (size_t)i * N) = make_float4(mx[i][0], mx[i][1], mx[i][2], mx[i][3]);
            *(float4*)(mnp + (size_t)i * N) = make_float4(mn[i][0], mn[i][1], mn[i][2], mn[i][3]);
        }

        // ---- arrival protocol ----
        __threadfence();                 // release partial stores (gpu scope)
        __syncthreads();                 // all threads' stores+fences done; orders smem reuse
        if (tid == 0) s_old = atomicAdd(&g_cnt[tile], 1u);
        __syncthreads();

        if (s_old == SPLITS - 1) {
            // ---- finisher: merge 4 partials + bias -> C (64x64 tile) ----
            __threadfence();             // acquire other CTAs' partials
            const int rowbase = mi * TBM;
            const int colbase = ni * TBN;
            // 4096 elems = 128 threads x 8 float4
#pragma unroll
            for (int it = 0; it < 8; ++it) {
                const int e = it * 512 + tid * 4;    // elem index within 64x64 tile
                const int r = e >> 6;
                const int c = e & 63;
                const size_t off = (size_t)(rowbase + r) * N + colbase + c;

                float4 x0 = *(const float4*)(g_mx[0] + off);
                float4 x1 = *(const float4*)(g_mx[1] + off);
                float4 x2 = *(const float4*)(g_mx[2] + off);
                float4 x3 = *(const float4*)(g_mx[3] + off);
                float4 n0 = *(const float4*)(g_mn[0] + off);
                float4 n1 = *(const float4*)(g_mn[1] + off);
                float4 n2 = *(const float4*)(g_mn[2] + off);
                float4 n3 = *(const float4*)(g_mn[3] + off);
                float4 bv = *(const float4*)&bias[colbase + c];

                float4 o;
                o.x = fmaxf(fmaxf(x0.x, x1.x), fmaxf(x2.x, x3.x)) + fminf(fminf(n0.x, n1.x), fminf(n2.x, n3.x)) + bv.x;
                o.y = fmaxf(fmaxf(x0.y, x1.y), fmaxf(x2.y, x3.y)) + fminf(fminf(n0.y, n1.y), fminf(n2.y, n3.y)) + bv.y;
                o.z = fmaxf(fmaxf(x0.z, x1.z), fmaxf(x2.z, x3.z)) + fminf(fminf(n0.z, n1.z), fminf(n2.z, n3.z)) + bv.z;
                o.w = fmaxf(fmaxf(x0.w, x1.w), fmaxf(x2.w, x3.w)) + fminf(fminf(n0.w, n1.w), fminf(n2.w, n3.w)) + bv.w;
                *(float4*)(C + off) = o;
            }
            if (tid == 0) g_cnt[tile] = 0;   // reset for next graph replay
        }
    }
}

extern "C" void kernel_launch(void* const* d_in, const int* in_sizes, int n_in,
                              void* d_out, int out_size)
{
    const float* x    = (const float*)d_in[0];   // [M, K]
    const float* w    = (const float*)d_in[1];   // [N, K]
    const float* bias = (const float*)d_in[2];   // [N]
    float* out = (float*)d_out;

    const int N = in_sizes[2];                  // 1024
    const int K = in_sizes[1] / N;              // 1024
    const int M = in_sizes[0] / K;              // 2048

    mam_kernel<<<NUM_CTAS, THREADS>>>(x, w, bias, out, M, N, K);
}